// round 17
// baseline (speedup 1.0000x reference)
#include <cuda_runtime.h>

// WKV7 (RWKV-7) recurrence, T=4096, H=32, N=64.
//
// v9: consumer = v7 (G=16 lanes/row, float4 state per lane, 2 rows/warp,
// 1024 warps; interleaved 4-level butterflies; all vectors prefetched one
// step ahead from the smem ring). Producer = cp.async.bulk: one elected
// thread per CTA issues 6 x 256B bulk copies per stage (48 per 8-step
// period), completion via 4 rotating mbarriers (expect_tx). This removes
// the per-thread LDGSTS storm (96/CTA-step in v5-v7) from the LSU.
// 128 CTAs x 256 threads: 16 rows of ONE head per CTA (4 CTAs/head).

#define TT 4096
#define HH 32
#define NN 64
#define CC (HH * NN)        // 2048 channels per timestep

#define SP 8                // steps per period
#define NGRP 4              // periods resident in the ring
#define STAGES (SP * NGRP)  // 32
#define SFLOATS 384         // 6 vectors x 64 floats per stage
#define STAGE_BYTES (SFLOATS * 4)          // 1536
#define PERIOD_TX (SP * 6 * 256)           // 12288 bytes per period
#define NPER (TT / SP)                     // 512

// smem layout (dynamic): [0..31] 4 mbarriers (8B each), [64..) stage ring
#define SMEM_TOTAL (64 + STAGES * STAGE_BYTES)   // 49216

__device__ __forceinline__ unsigned smem_u32(const void* p) {
    return (unsigned)__cvta_generic_to_shared(p);
}
__device__ __forceinline__ void mbar_init(unsigned mb, unsigned count) {
    asm volatile("mbarrier.init.shared.b64 [%0], %1;" :: "r"(mb), "r"(count) : "memory");
}
__device__ __forceinline__ void mbar_expect_tx(unsigned mb, unsigned bytes) {
    asm volatile("mbarrier.arrive.expect_tx.shared.b64 _, [%0], %1;"
                 :: "r"(mb), "r"(bytes) : "memory");
}
__device__ __forceinline__ void mbar_wait(unsigned mb, unsigned phase) {
    asm volatile(
        "{\n\t"
        ".reg .pred P;\n\t"
        "WAIT_%=: mbarrier.try_wait.parity.shared.b64 P, [%0], %1;\n\t"
        "@P bra DONE_%=;\n\t"
        "bra WAIT_%=;\n\t"
        "DONE_%=:\n\t"
        "}"
        :: "r"(mb), "r"(phase) : "memory");
}
__device__ __forceinline__ void bulk_cp256(unsigned dst, const float* src, unsigned mb) {
    asm volatile(
        "cp.async.bulk.shared::cluster.global.mbarrier::complete_tx::bytes "
        "[%0], [%1], 256, [%2];"
        :: "r"(dst), "l"(src), "r"(mb) : "memory");
}
__device__ __forceinline__ float dot4(float4 x, float4 y) {
    return fmaf(x.x, y.x, x.y * y.y) + fmaf(x.z, y.z, x.w * y.w);
}

__global__ __launch_bounds__(256) void wkv7_scan_kernel(
    const float* __restrict__ r, const float* __restrict__ w,
    const float* __restrict__ k, const float* __restrict__ v,
    const float* __restrict__ a, const float* __restrict__ b,
    const float* __restrict__ s0, float* __restrict__ out)
{
    extern __shared__ float smem[];
    float*   stageF   = smem + 16;                 // stage ring (floats)
    unsigned mbarBase = smem_u32(smem);            // 4 mbarriers at offset 0
    unsigned stageS   = smem_u32(smem) + 64;       // ring base (smem addr)

    const int tid  = threadIdx.x;
    const int cta  = blockIdx.x;           // 0..127
    const int h    = cta >> 2;             // 4 CTAs per head
    const int wid  = tid >> 5;             // 0..7
    const int lane = tid & 31;
    const int half = lane >> 4;            // which of the warp's 2 rows
    const int g    = lane & 15;            // lane within the row group
    const int i    = ((cta & 3) << 4) + (wid << 1) + half;  // row 0..63
    const int j0   = g << 2;               // this lane's 4 j-columns

    // ---- mbarrier init
    if (tid == 0) {
        #pragma unroll
        for (int s = 0; s < NGRP; ++s) mbar_init(mbarBase + s * 8, 1);
    }
    __syncthreads();

    // ---- producer: one thread per CTA issues 48 bulk copies per period
    const float* bases[6] = {r, w, k, a, b, v};
    auto issue_period = [&](int p) {
        if (tid == 0) {
            unsigned mb = mbarBase + (p & 3) * 8;
            mbar_expect_tx(mb, PERIOD_TX);
            #pragma unroll
            for (int u = 0; u < SP; ++u) {
                int t    = p * SP + u;
                int tc   = (t < TT) ? t : (TT - 1);
                int slot = t & (STAGES - 1);
                unsigned dst = stageS + slot * STAGE_BYTES;
                #pragma unroll
                for (int vec = 0; vec < 6; ++vec) {
                    bulk_cp256(dst + vec * 256,
                               bases[vec] + (size_t)tc * CC + h * NN, mb);
                }
            }
        }
    };

    // ---- initial state row chunk
    float4 s = *reinterpret_cast<const float4*>(
        s0 + ((size_t)(h * NN + i) * NN + j0));

    const int vibase = h * NN + i;         // v_i / y_i within a [C] vector

    // ---- prologue: issue periods 0,1,2; wait period 0
    issue_period(0);
    issue_period(1);
    issue_period(2);
    mbar_wait(mbarBase + 0, 0);

    // ---- prefetch step-0 vectors
    float4 Rv = *reinterpret_cast<const float4*>(&stageF[  0 + j0]);
    float4 Wv = *reinterpret_cast<const float4*>(&stageF[ 64 + j0]);
    float4 Kv = *reinterpret_cast<const float4*>(&stageF[128 + j0]);
    float4 Av = *reinterpret_cast<const float4*>(&stageF[192 + j0]);
    float4 Bv = *reinterpret_cast<const float4*>(&stageF[256 + j0]);
    float  V  = stageF[320 + i];

    float q = 0.0f;  // pending y-partial from previous step

    for (int hb = 0; hb < NPER; ++hb) {
        __syncthreads();                   // all done with period hb-1 slots
        issue_period(hb + 3);              // refill those slots
        // wait for period hb+1 (needed by the u=SP-1 prefetch)
        const int pw = hb + 1;
        mbar_wait(mbarBase + (pw & 3) * 8, (pw >> 2) & 1);

        const int tbase = hb * SP;
        #pragma unroll
        for (int u = 0; u < SP; ++u) {
            const int t  = tbase + u;
            const int sn = (t + 1) & (STAGES - 1);  // next step's stage
            const float* stg = stageF + sn * SFLOATS;

            // ---- prefetch t+1 vectors from smem
            float4 Rn = *reinterpret_cast<const float4*>(&stg[  0 + j0]);
            float4 Wn = *reinterpret_cast<const float4*>(&stg[ 64 + j0]);
            float4 Kn = *reinterpret_cast<const float4*>(&stg[128 + j0]);
            float4 an = *reinterpret_cast<const float4*>(&stg[192 + j0]);
            float4 bn = *reinterpret_cast<const float4*>(&stg[256 + j0]);
            float  Vn = stg[320 + i];

            // ---- sa partial for step t (state BEFORE update)
            float p = dot4(s, Av);

            // ---- interleaved 4-level butterflies (width 16):
            //      p (sa_t) and q (y_{t-1}) are independent.
            float ps, qs;
            ps = __shfl_xor_sync(0xffffffffu, p, 8);
            qs = __shfl_xor_sync(0xffffffffu, q, 8);
            p += ps;  q += qs;
            ps = __shfl_xor_sync(0xffffffffu, p, 4);
            qs = __shfl_xor_sync(0xffffffffu, q, 4);
            p += ps;  q += qs;
            ps = __shfl_xor_sync(0xffffffffu, p, 2);
            qs = __shfl_xor_sync(0xffffffffu, q, 2);
            p += ps;  q += qs;
            ps = __shfl_xor_sync(0xffffffffu, p, 1);
            qs = __shfl_xor_sync(0xffffffffu, q, 1);
            p += ps;  q += qs;

            // ---- emit y for step t-1
            if (g == 0 && t > 0) {
                out[(size_t)(t - 1) * CC + vibase] = q;
            }

            // ---- state update: s = s*w + v_i*k + sa*b
            s.x = fmaf(p, Bv.x, fmaf(V, Kv.x, s.x * Wv.x));
            s.y = fmaf(p, Bv.y, fmaf(V, Kv.y, s.y * Wv.y));
            s.z = fmaf(p, Bv.z, fmaf(V, Kv.z, s.z * Wv.z));
            s.w = fmaf(p, Bv.w, fmaf(V, Kv.w, s.w * Wv.w));

            // ---- y partial for step t (reduced during step t+1)
            q = dot4(s, Rv);

            // rotate
            Rv = Rn; Wv = Wn; Kv = Kn; Av = an; Bv = bn; V = Vn;
        }
    }

    // ---- final y reduction (step T-1)
    q += __shfl_xor_sync(0xffffffffu, q, 8);
    q += __shfl_xor_sync(0xffffffffu, q, 4);
    q += __shfl_xor_sync(0xffffffffu, q, 2);
    q += __shfl_xor_sync(0xffffffffu, q, 1);
    if (g == 0) {
        out[(size_t)(TT - 1) * CC + vibase] = q;
    }

    // ---- final state
    *reinterpret_cast<float4*>(out + (size_t)TT * CC +
                               ((size_t)(h * NN + i) * NN + j0)) = s;
}

// Input order (metadata): seq_length(int32), r, w, k, v, a, b, state2.
// Output: concat(x[T,H,1,N], state2_out[H,N,N]) as float32.
extern "C" void kernel_launch(void* const* d_in, const int* in_sizes, int n_in,
                              void* d_out, int out_size)
{
    const float* r  = (const float*)d_in[1];
    const float* w  = (const float*)d_in[2];
    const float* k  = (const float*)d_in[3];
    const float* v  = (const float*)d_in[4];
    const float* a  = (const float*)d_in[5];
    const float* b  = (const float*)d_in[6];
    const float* s0 = (const float*)d_in[7];
    float* out = (float*)d_out;

    static int smem_set = 0;
    if (!smem_set) {
        cudaFuncSetAttribute(wkv7_scan_kernel,
                             cudaFuncAttributeMaxDynamicSharedMemorySize,
                             SMEM_TOTAL);
        smem_set = 1;
    }
    // 128 CTAs x 256 threads = 1024 warps (2 rows per warp)
    wkv7_scan_kernel<<<128, 256, SMEM_TOTAL>>>(r, w, k, v, a, b, s0, out);
}